// round 6
// baseline (speedup 1.0000x reference)
#include <cuda_runtime.h>
#include <cuda_bf16.h>

#define Cc    9
#define OUTc  16
#define NBc   16
#define Vc    20000
#define Bc    2
#define RSTR  8          // row stride in float4: 128 B = one cache line

// per-row table: [x0..3 | x4..7 | x8,en8,ep8,0 | en-even | en-odd | ep-even | ep-odd | pad]
__device__ __align__(128) float4 xtab[Bc * Vc * RSTR];

__global__ __launch_bounds__(256)
void pad_kernel(const float* __restrict__ x)
{
    int r = blockIdx.x * blockDim.x + threadIdx.x;   // row over B*V
    if (r >= Bc * Vc) return;
    const float* src = x + (size_t)r * Cc;
    float xv[Cc], en[Cc], ep[Cc];
    #pragma unroll
    for (int c = 0; c < Cc; c++) {
        xv[c] = src[c];
        ep[c] = __expf(xv[c]);
        en[c] = __expf(-xv[c]);
    }
    float4* dst = xtab + (size_t)r * RSTR;
    dst[0] = make_float4(xv[0], xv[1], xv[2], xv[3]);
    dst[1] = make_float4(xv[4], xv[5], xv[6], xv[7]);
    dst[2] = make_float4(xv[8], en[8], ep[8], 0.0f);
    dst[3] = make_float4(en[0], en[2], en[4], en[6]);   // en even  (k=0,2,4,6)
    dst[4] = make_float4(en[1], en[3], en[5], en[7]);   // en odd   (k=1,3,5,7)
    dst[5] = make_float4(ep[0], ep[2], ep[4], ep[6]);   // ep even
    dst[6] = make_float4(ep[1], ep[3], ep[5], ep[7]);   // ep odd
    dst[7] = make_float4(0.0f, 0.0f, 0.0f, 0.0f);
}

__global__ __launch_bounds__(128, 4)
void nlayer_kernel(const float* __restrict__ W,
                   const int*   __restrict__ adj,
                   float*       __restrict__ out)
{
    // Wsh padded: p=1,j=4 dead slot reads rows up to index 1296+15; pad zeroed
    __shared__ float Wsh[Cc * Cc * OUTc + 16];
    for (int i = threadIdx.x; i < Cc * Cc * OUTc + 16; i += blockDim.x)
        Wsh[i] = (i < Cc * Cc * OUTc) ? W[i] : 0.0f;
    __syncthreads();

    int tid   = blockIdx.x * blockDim.x + threadIdx.x;
    int group = tid >> 2;          // vertex over B*V
    int l     = tid & 3;
    int p     = l & 1;             // k-parity: lane handles k = 2j + p
    int q     = l >> 1;            // neighbor half + output half

    int b = (group >= Vc) ? 1 : 0;
    int v = group - b * Vc;
    const float4* tb = xtab + (size_t)(b * Vc) * RSTR;

    // center: this lane's ep parity (5 values; p=1 5th is 0)
    const float4* cr = tb + (size_t)v * RSTR;
    float4 cep4 = __ldg(&cr[5 + p]);
    float  cepl = (p == 0) ? __ldg(&cr[2]).z : 0.0f;

    // this lane's neighbor half: neighbors [8q, 8q+8)
    const int4* adj4 = reinterpret_cast<const int4*>(adj + (size_t)v * NBc);
    int4 a0 = __ldg(&adj4[2 * q + 0]);
    int4 a1 = __ldg(&adj4[2 * q + 1]);
    int a[8] = {a0.x, a0.y, a0.z, a0.w, a1.x, a1.y, a1.z, a1.w};

    // s'[j][c] = sum_n (en[n,k]*r_n) * nbv[n,c],  k = 2j + p
    float s[5][Cc];
    #pragma unroll
    for (int j = 0; j < 5; j++)
        #pragma unroll
        for (int c = 0; c < Cc; c++) s[j][c] = 0.0f;

    int deg = 0;

    #pragma unroll
    for (int n = 0; n < 8; n++) {
        int an    = a[n];
        int valid = (an != 0);
        deg += valid;
        int ridx = valid ? (an - 1) : 0;

        const float4* nr = tb + (size_t)ridx * RSTR;   // one 128B line
        float4 x0 = __ldg(&nr[0]);
        float4 x1 = __ldg(&nr[1]);
        float4 x2 = __ldg(&nr[2]);
        float4 e4 = __ldg(&nr[3 + p]);                 // lane's en parity
        float  el = (p == 0) ? x2.y : 0.0f;            // en[8] or dead slot

        float nbv[Cc] = {x0.x, x0.y, x0.z, x0.w, x1.x, x1.y, x1.z, x1.w, x2.x};

        // parity-partial softmax denominator, combined across the p-pair
        float part = cep4.x * e4.x;
        part = fmaf(cep4.y, e4.y, part);
        part = fmaf(cep4.z, e4.z, part);
        part = fmaf(cep4.w, e4.w, part);
        part = fmaf(cepl,   el,   part);
        part += __shfl_xor_sync(0xffffffffu, part, 1);

        float r = valid ? __fdividef(1.0f, part) : 0.0f;

        float g[5] = {e4.x * r, e4.y * r, e4.z * r, e4.w * r, el * r};

        #pragma unroll
        for (int j = 0; j < 5; j++)
            #pragma unroll
            for (int c = 0; c < Cc; c++)
                s[j][c] = fmaf(g[j], nbv[c], s[j][c]);
    }

    // reduce over the two neighbor halves
    deg += __shfl_xor_sync(0xffffffffu, deg, 2);
    #pragma unroll
    for (int j = 0; j < 5; j++)
        #pragma unroll
        for (int c = 0; c < Cc; c++)
            s[j][c] += __shfl_xor_sync(0xffffffffu, s[j][c], 2);

    float invdeg = (deg > 0) ? (1.0f / (float)deg) : 0.0f;

    // contraction: lane's k-parity slice into its o-half [8q, 8q+8)
    // s[k][c] = ep[k] * s'[k][c];  ep parity values are cep4 / cepl
    float epar[5] = {cep4.x, cep4.y, cep4.z, cep4.w, cepl};

    float acc[8];
    #pragma unroll
    for (int o = 0; o < 8; o++) acc[o] = 0.0f;

    const float* wbase = Wsh + 16 * p + 8 * q;   // folds k=2j+p and o-half
    #pragma unroll
    for (int c = 0; c < Cc; c++) {
        #pragma unroll
        for (int j = 0; j < 5; j++) {
            float sc = s[j][c] * epar[j];        // exactly 0 for dead slot
            const float* wrow = wbase + (c * Cc + 2 * j) * OUTc;
            float4 w0 = *reinterpret_cast<const float4*>(wrow);
            float4 w1 = *reinterpret_cast<const float4*>(wrow + 4);
            acc[0] = fmaf(sc, w0.x, acc[0]);
            acc[1] = fmaf(sc, w0.y, acc[1]);
            acc[2] = fmaf(sc, w0.z, acc[2]);
            acc[3] = fmaf(sc, w0.w, acc[3]);
            acc[4] = fmaf(sc, w1.x, acc[4]);
            acc[5] = fmaf(sc, w1.y, acc[5]);
            acc[6] = fmaf(sc, w1.z, acc[6]);
            acc[7] = fmaf(sc, w1.w, acc[7]);
        }
    }

    // combine k-parities; both p-lanes of a q-half then hold the full o-half
    #pragma unroll
    for (int o = 0; o < 8; o++)
        acc[o] += __shfl_xor_sync(0xffffffffu, acc[o], 1);

    // lane l stores o in [4l, 4l+4)  (4l == 8q + 4p) -> 512B contiguous per warp
    int ob = 4 * p;
    float4 rout;
    rout.x = fmaxf(acc[ob + 0] * invdeg, 0.0f);
    rout.y = fmaxf(acc[ob + 1] * invdeg, 0.0f);
    rout.z = fmaxf(acc[ob + 2] * invdeg, 0.0f);
    rout.w = fmaxf(acc[ob + 3] * invdeg, 0.0f);

    *reinterpret_cast<float4*>(out + (size_t)group * OUTc + 4 * l) = rout;
}

extern "C" void kernel_launch(void* const* d_in, const int* in_sizes, int n_in,
                              void* d_out, int out_size)
{
    const float* x   = (const float*)d_in[0];   // (2, 20000, 9)
    const float* W   = (const float*)d_in[1];   // (9, 9, 16)
    const int*   adj = (const int*)d_in[2];     // (20000, 16)
    float*       out = (float*)d_out;           // (2, 20000, 16)

    {
        const int total   = Bc * Vc;            // 40000
        const int threads = 256;
        pad_kernel<<<(total + threads - 1) / threads, threads>>>(x);
    }
    {
        const int total   = Bc * Vc * 4;        // 160000
        const int threads = 128;
        nlayer_kernel<<<(total + threads - 1) / threads, threads>>>(W, adj, out);
    }
}

// round 7
// speedup vs baseline: 1.0780x; 1.0780x over previous
#include <cuda_runtime.h>
#include <cuda_bf16.h>

#define Cc    9
#define OUTc  16
#define NBc   16
#define Vc    20000
#define Bc    2

// padded x: 3 float4 per row (48 B)
__device__ __align__(16) float4 xpad[Bc * Vc * 3];

__global__ __launch_bounds__(256)
void pad_kernel(const float* __restrict__ x)
{
    int r = blockIdx.x * blockDim.x + threadIdx.x;   // row over B*V
    if (r >= Bc * Vc) return;
    const float* src = x + (size_t)r * Cc;
    float4* dst = xpad + (size_t)r * 3;
    dst[0] = make_float4(__ldg(&src[0]), __ldg(&src[1]), __ldg(&src[2]), __ldg(&src[3]));
    dst[1] = make_float4(__ldg(&src[4]), __ldg(&src[5]), __ldg(&src[6]), __ldg(&src[7]));
    dst[2] = make_float4(__ldg(&src[8]), 0.0f, 0.0f, 0.0f);
}

__global__ __launch_bounds__(128, 4)
void nlayer_kernel(const float* __restrict__ W,
                   const int*   __restrict__ adj,
                   float*       __restrict__ out)
{
    // padded so the dead k=9 slot reads zeros
    __shared__ float Wsh[Cc * Cc * OUTc + 16];
    for (int i = threadIdx.x; i < Cc * Cc * OUTc + 16; i += blockDim.x)
        Wsh[i] = (i < Cc * Cc * OUTc) ? W[i] : 0.0f;
    __syncthreads();

    int tid   = blockIdx.x * blockDim.x + threadIdx.x;   // 320000 total, exact
    int group = tid >> 3;          // vertex over B*V
    int l     = tid & 7;
    int p     = l & 1;             // k-half: k = 5p + j, j<5 (p=1,j=4 dead)
    int q     = l >> 1;            // neighbor quarter (4 neighbors) + o-quarter

    int b = (group >= Vc) ? 1 : 0;
    int v = group - b * Vc;
    const float4* tb = xpad + (size_t)(b * Vc) * 3;

    // ---- load burst: everything independent, issued up front ----
    // center row (all 8 lanes same address -> merged)
    float4 c0 = __ldg(&tb[(size_t)v * 3 + 0]);
    float4 c1 = __ldg(&tb[(size_t)v * 3 + 1]);
    float4 c2 = __ldg(&tb[(size_t)v * 3 + 2]);

    // this lane's 4 neighbors
    int4 av = __ldg(reinterpret_cast<const int4*>(adj + (size_t)v * NBc) + q);
    int a[4] = {av.x, av.y, av.z, av.w};

    float4 r0[4], r1[4], r2[4];
    int valid[4];
    int deg = 0;
    #pragma unroll
    for (int n = 0; n < 4; n++) {
        valid[n] = (a[n] != 0);
        deg += valid[n];
        int ridx = valid[n] ? (a[n] - 1) : 0;
        const float4* nr = tb + (size_t)ridx * 3;
        r0[n] = __ldg(&nr[0]);
        r1[n] = __ldg(&nr[1]);
        r2[n] = __ldg(&nr[2]);
    }

    // center features for this lane's k-half
    float xc[5];
    if (p == 0) { xc[0]=c0.x; xc[1]=c0.y; xc[2]=c0.z; xc[3]=c0.w; xc[4]=c1.x; }
    else        { xc[0]=c1.y; xc[1]=c1.z; xc[2]=c1.w; xc[3]=c2.x; xc[4]=0.0f; }

    // ---- compute phase: s'[j][c] = sum_n q[n,5p+j] * nbv[n,c] ----
    float s[5][Cc];
    #pragma unroll
    for (int j = 0; j < 5; j++)
        #pragma unroll
        for (int c = 0; c < Cc; c++) s[j][c] = 0.0f;

    #pragma unroll
    for (int n = 0; n < 4; n++) {
        float nbv[Cc] = {r0[n].x, r0[n].y, r0[n].z, r0[n].w,
                         r1[n].x, r1[n].y, r1[n].z, r1[n].w, r2[n].x};

        float e[5];
        if (p == 0) {
            e[0] = __expf(xc[0] - nbv[0]);
            e[1] = __expf(xc[1] - nbv[1]);
            e[2] = __expf(xc[2] - nbv[2]);
            e[3] = __expf(xc[3] - nbv[3]);
            e[4] = __expf(xc[4] - nbv[4]);
        } else {
            e[0] = __expf(xc[0] - nbv[5]);
            e[1] = __expf(xc[1] - nbv[6]);
            e[2] = __expf(xc[2] - nbv[7]);
            e[3] = __expf(xc[3] - nbv[8]);
            e[4] = 0.0f;
        }

        float part = e[0] + e[1] + e[2] + e[3] + e[4];
        part += __shfl_xor_sync(0xffffffffu, part, 1);     // combine k-halves
        float rr = valid[n] ? __fdividef(1.0f, part) : 0.0f;

        #pragma unroll
        for (int j = 0; j < 5; j++) {
            float g = e[j] * rr;
            #pragma unroll
            for (int c = 0; c < Cc; c++)
                s[j][c] = fmaf(g, nbv[c], s[j][c]);
        }
    }

    // reduce s and deg over the 4 neighbor quarters
    deg += __shfl_xor_sync(0xffffffffu, deg, 2);
    deg += __shfl_xor_sync(0xffffffffu, deg, 4);
    #pragma unroll
    for (int j = 0; j < 5; j++)
        #pragma unroll
        for (int c = 0; c < Cc; c++) {
            float t = s[j][c];
            t += __shfl_xor_sync(0xffffffffu, t, 2);
            t += __shfl_xor_sync(0xffffffffu, t, 4);
            s[j][c] = t;
        }

    float invdeg = (deg > 0) ? (1.0f / (float)deg) : 0.0f;

    // contraction: lane's k-half into o-quarter [4q, 4q+4)
    float acc[4] = {0.0f, 0.0f, 0.0f, 0.0f};
    const float* wb = Wsh + 80 * p + 4 * q;   // (5p+j)*16 + 4q folded
    #pragma unroll
    for (int c = 0; c < Cc; c++) {
        #pragma unroll
        for (int j = 0; j < 5; j++) {
            float sc = s[j][c];
            float4 w = *reinterpret_cast<const float4*>(wb + c * 144 + j * 16);
            acc[0] = fmaf(sc, w.x, acc[0]);
            acc[1] = fmaf(sc, w.y, acc[1]);
            acc[2] = fmaf(sc, w.z, acc[2]);
            acc[3] = fmaf(sc, w.w, acc[3]);
        }
    }

    // combine the two k-halves; both p-lanes then hold the full o-quarter
    #pragma unroll
    for (int o = 0; o < 4; o++)
        acc[o] += __shfl_xor_sync(0xffffffffu, acc[o], 1);

    // lane stores 2 outputs at o = 4q + 2p  -> 256B contiguous per warp
    float2 st;
    st.x = fmaxf(((p == 0) ? acc[0] : acc[2]) * invdeg, 0.0f);
    st.y = fmaxf(((p == 0) ? acc[1] : acc[3]) * invdeg, 0.0f);
    *reinterpret_cast<float2*>(out + (size_t)group * OUTc + 4 * q + 2 * p) = st;
}

extern "C" void kernel_launch(void* const* d_in, const int* in_sizes, int n_in,
                              void* d_out, int out_size)
{
    const float* x   = (const float*)d_in[0];   // (2, 20000, 9)
    const float* W   = (const float*)d_in[1];   // (9, 9, 16)
    const int*   adj = (const int*)d_in[2];     // (20000, 16)
    float*       out = (float*)d_out;           // (2, 20000, 16)

    {
        const int total   = Bc * Vc;            // 40000
        const int threads = 256;
        pad_kernel<<<(total + threads - 1) / threads, threads>>>(x);
    }
    {
        const int total   = Bc * Vc * 8;        // 320000
        const int threads = 128;
        nlayer_kernel<<<total / threads, threads>>>(W, adj, out);
    }
}